// round 13
// baseline (speedup 1.0000x reference)
#include <cuda_runtime.h>
#include <cstddef>

#define Bb 8
#define Tt 2048
#define Dd 512
#define Hh 512
#define FOURH 2048
#define GRID_R 128
#define DOM_BLKS 32          // blocks per sync domain (2 batches per domain)

typedef unsigned long long u64;

// ---------------- scratch (static device globals: allocation-free) ----------------
__device__ float g_wx[(size_t)Bb * Tt * FOURH];   // 128 MiB: precomputed x @ W^T + b
__device__ float g_h[2][Bb * Hh];                 // double-buffered hidden state
__device__ unsigned g_cnt4[4 * 32];               // 4 per-domain counters, 128B apart

// ---------------- packed f32x2 helpers (b64 regs via "l" constraint) ----------------
__device__ __forceinline__ void fma2(u64 &acc, u64 a, u64 b) {
    asm("fma.rn.f32x2 %0, %1, %2, %0;" : "+l"(acc) : "l"(a), "l"(b));
}
__device__ __forceinline__ void unpack2(u64 v, float &lo, float &hi) {
    asm("mov.b64 {%0, %1}, %2;" : "=f"(lo), "=f"(hi) : "l"(v));
}

// ---------------- scoped sync primitives ----------------
__device__ __forceinline__ void cnt_arrive_release(unsigned* p) {
    asm volatile("red.release.gpu.global.add.u32 [%0], %1;"
                 :: "l"(p), "r"(1u) : "memory");
}
__device__ __forceinline__ unsigned ld_acquire(const unsigned* p) {
    unsigned v;
    asm volatile("ld.acquire.gpu.global.u32 %0, [%1];"
                 : "=r"(v) : "l"(p) : "memory");
    return v;
}

// ---------------- fast gate math (MUFU-based) ----------------
__device__ __forceinline__ float sigm_f(float x) {
    return __fdividef(1.f, 1.f + __expf(-x));
}
__device__ __forceinline__ float tanh_f(float x) {
    float e = __expf(2.f * x);
    return 1.f - __fdividef(2.f, e + 1.f);
}

// ---------------- tf32 helpers ----------------
__device__ __forceinline__ unsigned tf32cvt(float f) {
    unsigned r; asm("cvt.rna.tf32.f32 %0, %1;" : "=r"(r) : "f"(f)); return r;
}
__device__ __forceinline__ void mma_tf32(float* d, const unsigned* a, const unsigned* b) {
    asm("mma.sync.aligned.m16n8k8.row.col.f32.tf32.tf32.f32 "
        "{%0,%1,%2,%3}, {%4,%5,%6,%7}, {%8,%9}, {%0,%1,%2,%3};"
        : "+f"(d[0]), "+f"(d[1]), "+f"(d[2]), "+f"(d[3])
        : "r"(a[0]), "r"(a[1]), "r"(a[2]), "r"(a[3]), "r"(b[0]), "r"(b[1]));
}

// =====================================================================
// Kernel 1 (tf32 tensor cores): Wx = x @ W_w^T + W_b   (R9 verbatim)
// =====================================================================
__global__ void __launch_bounds__(256) gemm_wx_tf32_kernel(
    const float* __restrict__ x, const float* __restrict__ Ww,
    const float* __restrict__ Wb)
{
    __shared__ __align__(16) unsigned As[128][36];
    __shared__ __align__(16) unsigned Bs[128][36];

    const int tid  = threadIdx.x;
    const int w    = tid >> 5;
    const int lane = tid & 31;
    const int g    = lane >> 2;
    const int tig  = lane & 3;
    const int wm   = w >> 1;
    const int wn   = w & 1;
    const int m0   = blockIdx.y * 128;
    const int n0   = blockIdx.x * 128;

    const int lr = tid >> 1;
    const int lh = tid & 1;

    float acc[2][8][4];
    #pragma unroll
    for (int mt = 0; mt < 2; mt++)
        #pragma unroll
        for (int nt = 0; nt < 8; nt++)
            #pragma unroll
            for (int c = 0; c < 4; c++) acc[mt][nt][c] = 0.f;

    float4 ra[4], rb[4];
    {
        const float* pa = &x [(size_t)(m0 + lr) * 512 + lh * 16];
        const float* pb = &Ww[(size_t)(n0 + lr) * 512 + lh * 16];
        #pragma unroll
        for (int q = 0; q < 4; q++) {
            ra[q] = *(const float4*)(pa + 4 * q);
            rb[q] = *(const float4*)(pb + 4 * q);
        }
    }

    for (int chunk = 0; chunk < 16; chunk++) {
        __syncthreads();
        {
            const float* fa = (const float*)ra;
            const float* fb = (const float*)rb;
            #pragma unroll
            for (int g8 = 0; g8 < 2; g8++) {
                const int base = lh * 16 + g8 * 8;
                const float* f = fa + g8 * 8;
                uint4 v0 = make_uint4(tf32cvt(f[0]), tf32cvt(f[4]), tf32cvt(f[1]), tf32cvt(f[5]));
                uint4 v1 = make_uint4(tf32cvt(f[2]), tf32cvt(f[6]), tf32cvt(f[3]), tf32cvt(f[7]));
                *(uint4*)&As[lr][base]     = v0;
                *(uint4*)&As[lr][base + 4] = v1;
                const float* fw = fb + g8 * 8;
                uint4 w0 = make_uint4(tf32cvt(fw[0]), tf32cvt(fw[4]), tf32cvt(fw[1]), tf32cvt(fw[5]));
                uint4 w1 = make_uint4(tf32cvt(fw[2]), tf32cvt(fw[6]), tf32cvt(fw[3]), tf32cvt(fw[7]));
                *(uint4*)&Bs[lr][base]     = w0;
                *(uint4*)&Bs[lr][base + 4] = w1;
            }
        }
        __syncthreads();

        if (chunk < 15) {
            const int kc = (chunk + 1) * 32;
            const float* pa = &x [(size_t)(m0 + lr) * 512 + kc + lh * 16];
            const float* pb = &Ww[(size_t)(n0 + lr) * 512 + kc + lh * 16];
            #pragma unroll
            for (int q = 0; q < 4; q++) {
                ra[q] = *(const float4*)(pa + 4 * q);
                rb[q] = *(const float4*)(pb + 4 * q);
            }
        }

        #pragma unroll
        for (int s = 0; s < 4; s++) {
            const int koff = 8 * s + 2 * tig;
            unsigned afrag[2][4];
            #pragma unroll
            for (int mt = 0; mt < 2; mt++) {
                const int rowA = wm * 32 + mt * 16 + g;
                uint2 p1 = *(const uint2*)&As[rowA][koff];
                uint2 p2 = *(const uint2*)&As[rowA + 8][koff];
                afrag[mt][0] = p1.x; afrag[mt][1] = p2.x;
                afrag[mt][2] = p1.y; afrag[mt][3] = p2.y;
            }
            #pragma unroll
            for (int nt = 0; nt < 8; nt++) {
                const int rowB = wn * 64 + nt * 8 + g;
                uint2 bp = *(const uint2*)&Bs[rowB][koff];
                unsigned bfrag[2] = { bp.x, bp.y };
                mma_tf32(acc[0][nt], afrag[0], bfrag);
                mma_tf32(acc[1][nt], afrag[1], bfrag);
            }
        }
    }

    #pragma unroll
    for (int nt = 0; nt < 8; nt++) {
        const int colD = n0 + wn * 64 + nt * 8 + 2 * tig;
        const float2 wb2 = *(const float2*)&Wb[colD];
        #pragma unroll
        for (int mt = 0; mt < 2; mt++) {
            const int rowD = m0 + wm * 32 + mt * 16 + g;
            float2 lo = make_float2(acc[mt][nt][0] + wb2.x, acc[mt][nt][1] + wb2.y);
            float2 hi = make_float2(acc[mt][nt][2] + wb2.x, acc[mt][nt][3] + wb2.y);
            *(float2*)&g_wx[(size_t)rowD * FOURH + colD]       = lo;
            *(float2*)&g_wx[(size_t)(rowD + 8) * FOURH + colD] = hi;
        }
    }
}

// =====================================================================
// Kernel 2: persistent recurrent sLSTM, 4 sync domains, distributed
// finalize, LEAN SYNC: all-warp poll -> per-warp stage -> one sync ->
// compute -> h store -> named-barrier arrive (non-blocking for 15 warps;
// warp 0 syncs and fires the single release-RED per block).
// =====================================================================
__global__ void __launch_bounds__(512) lstm_rec_kernel(
    const float* __restrict__ Uw, const float* __restrict__ Ub,
    const float* __restrict__ alpha, float* __restrict__ out)
{
    __shared__ __align__(16) float h_s[2][2][Hh];  // double-buffered 2 h rows (8 KB)

    const int tid  = threadIdx.x;
    const int w    = tid >> 5;
    const int lane = tid & 31;
    const int blk  = blockIdx.x;
    const int dom  = blk >> 5;
    const int j0   = (blk & 31) * 16;
    const int B0   = 2 * dom;
    const int jg   = j0 + w;        // this warp's hidden unit

    // lane slot: m = (lane>>2)&7 -> gate, batch-half
    const int m    = (lane >> 2) & 7;
    const int g_l  = m & 3;
    const int bi_l = m >> 2;
    const int Bf   = B0 + bi_l;

    // U_w register-resident: rows (g, jg) g=0..3; lane cols 4*lane + 128*q
    ulonglong2 u[4][4];
    #pragma unroll
    for (int g = 0; g < 4; g++)
        #pragma unroll
        for (int q = 0; q < 4; q++)
            u[g][q] = *(const ulonglong2*)&Uw[(size_t)(g * Hh + jg) * Hh + 128 * q + 4 * lane];

    const float ub_r    = Ub[g_l * Hh + jg];
    const float alpha_r = alpha[jg];
    float c_st = 0.f;               // live in lanes 0 (batch B0) and 16 (B0+1)

    unsigned* const my_cnt = &g_cnt4[dom * 32];

    // publish h0 = 0 (warp 0 zeroes this block's 32 floats, releases arrival)
    if (w == 0) {
        g_h[0][(B0 + (lane & 1)) * Hh + j0 + (lane >> 1)] = 0.f;
        __syncwarp();
        if (lane == 0) cnt_arrive_release(my_cnt);
    }

    for (int t = 0; t < Tt; ++t) {
        // prefetch Wx_t for this lane's slot (independent of h)
        const float wx = __ldg(&g_wx[((size_t)Bf * Tt + t) * FOURH + g_l * Hh + jg]);

        // ---- all-warp poll: this domain's 32 blocks published h_t
        {
            const unsigned tgt = (unsigned)DOM_BLKS * (unsigned)(t + 1);
            int spins = 0;
            while (ld_acquire(my_cnt) < tgt) {
                if (++spins > 64) __nanosleep(64);
            }
        }

        // ---- stage this warp's 256B share immediately (float2 per thread)
        {
            const float2* src = (const float2*)&g_h[t & 1][B0 * Hh];
            ((float2*)&h_s[t & 1][0][0])[tid] = __ldcg(&src[tid]);
        }
        __syncthreads();   // staged 4 KB complete

        // ---- dots: 4 gates x 2 batches over full 512 cols (from smem)
        u64 acc[4][2];
        #pragma unroll
        for (int g = 0; g < 4; g++) { acc[g][0] = 0ull; acc[g][1] = 0ull; }
        #pragma unroll
        for (int b2 = 0; b2 < 2; b2++) {
            #pragma unroll
            for (int q = 0; q < 4; q++) {
                ulonglong2 h2 = *(const ulonglong2*)&h_s[t & 1][b2][128 * q + 4 * lane];
                #pragma unroll
                for (int g = 0; g < 4; g++) {
                    fma2(acc[g][b2], u[g][q].x, h2.x);
                    fma2(acc[g][b2], u[g][q].y, h2.y);
                }
            }
        }

        // collapse pair halves -> v[mm], mm = gate + 4*batchhalf
        float v[8];
        #pragma unroll
        for (int g = 0; g < 4; g++)
            #pragma unroll
            for (int b2 = 0; b2 < 2; b2++) {
                float lo, hi; unpack2(acc[g][b2], lo, hi);
                v[g + 4 * b2] = lo + hi;
            }

        // 9-shfl butterfly: lane L ends with total for mm = (L>>2)&7
        {
            const bool up16 = (lane & 16) != 0;
            #pragma unroll
            for (int i = 0; i < 4; i++) {
                float a = v[i], bv = v[i + 4];
                float mine = up16 ? bv : a, oth = up16 ? a : bv;
                v[i] = mine + __shfl_xor_sync(0xffffffffu, oth, 16);
            }
            const bool up8 = (lane & 8) != 0;
            #pragma unroll
            for (int i = 0; i < 2; i++) {
                float a = v[i], bv = v[i + 2];
                float mine = up8 ? bv : a, oth = up8 ? a : bv;
                v[i] = mine + __shfl_xor_sync(0xffffffffu, oth, 8);
            }
            const bool up4 = (lane & 4) != 0;
            {
                float a = v[0], bv = v[1];
                float mine = up4 ? bv : a, oth = up4 ? a : bv;
                v[0] = mine + __shfl_xor_sync(0xffffffffu, oth, 4);
            }
            v[0] += __shfl_xor_sync(0xffffffffu, v[0], 2);
            v[0] += __shfl_xor_sync(0xffffffffu, v[0], 1);
        }

        // parallel activations: each lane activates its own slot
        const float z = v[0] + wx + ub_r;
        const float a = (g_l == 3) ? tanh_f(z) : sigm_f(z);

        // gather i/f/o/g at lanes 0 (bi=0) and 16 (bi=1); update c; store h
        const float a_f = __shfl_down_sync(0xffffffffu, a, 4);
        const float a_o = __shfl_down_sync(0xffffffffu, a, 8);
        const float a_g = __shfl_down_sync(0xffffffffu, a, 12);
        float hv = 0.f;
        if ((lane & 15) == 0) {
            c_st = alpha_r * (a_f * c_st + a * a_g);
            hv = a_o * tanh_f(c_st);
            g_h[(t + 1) & 1][Bf * Hh + jg] = hv;
        }

        // ---- arrival: warps 1..15 arrive without blocking; warp 0 waits,
        //      then fires the block's single release-RED.
        if (w == 0) {
            asm volatile("bar.sync 1, 512;" ::: "memory");
            if (lane == 0) cnt_arrive_release(my_cnt);
        } else {
            asm volatile("bar.arrive 1, 512;" ::: "memory");
        }

        // off-critical-path stores (kernel-end fence covers visibility)
        if ((lane & 15) == 0) {
            out[((size_t)Bf * Tt + t) * Hh + jg] = hv;
            if (t == Tt - 1) {
                out[(size_t)Bb * Tt * Hh + Bf * Hh + jg] = hv;                      // final h
                out[(size_t)Bb * Tt * Hh + (size_t)Bb * Hh + Bf * Hh + jg] = c_st;  // final c
            }
        }
    }

    // domain's slice-0 block resets its counter once all arrivals landed
    if ((blk & 31) == 0 && tid == 0) {
        const unsigned fin = (unsigned)DOM_BLKS * (unsigned)(Tt + 1);
        int spins = 0;
        while (ld_acquire(my_cnt) < fin) {
            if (++spins > 64) __nanosleep(128);
        }
        *my_cnt = 0u;
    }
}

// =====================================================================
extern "C" void kernel_launch(void* const* d_in, const int* in_sizes, int n_in,
                              void* d_out, int out_size)
{
    const float* x     = (const float*)d_in[0];
    const float* Ww    = (const float*)d_in[1];
    const float* Wb    = (const float*)d_in[2];
    const float* Uw    = (const float*)d_in[3];
    const float* Ub    = (const float*)d_in[4];
    const float* alpha = (const float*)d_in[5];
    float* out = (float*)d_out;

    dim3 ggrid(FOURH / 128, (Bb * Tt) / 128);   // 16 x 128
    gemm_wx_tf32_kernel<<<ggrid, 256>>>(x, Ww, Wb);
    lstm_rec_kernel<<<GRID_R, 512>>>(Uw, Ub, alpha, out);
}

// round 14
// speedup vs baseline: 1.0699x; 1.0699x over previous
#include <cuda_runtime.h>
#include <cstddef>

#define Bb 8
#define Tt 2048
#define Dd 512
#define Hh 512
#define FOURH 2048
#define GRID_R 128
#define DOM_BLKS 32          // blocks per sync domain (2 batches per domain)

typedef unsigned long long u64;

// ---------------- scratch (static device globals: allocation-free) ----------------
__device__ float g_wx[(size_t)Bb * Tt * FOURH];   // 128 MiB: precomputed x @ W^T + b
__device__ float g_h[2][Bb * Hh];                 // double-buffered hidden state
__device__ unsigned g_cnt4[4 * 32];               // 4 per-domain counters, 128B apart

// ---------------- packed f32x2 helpers (b64 regs via "l" constraint) ----------------
__device__ __forceinline__ void fma2(u64 &acc, u64 a, u64 b) {
    asm("fma.rn.f32x2 %0, %1, %2, %0;" : "+l"(acc) : "l"(a), "l"(b));
}
__device__ __forceinline__ void unpack2(u64 v, float &lo, float &hi) {
    asm("mov.b64 {%0, %1}, %2;" : "=f"(lo), "=f"(hi) : "l"(v));
}

// ---------------- scoped sync primitives ----------------
__device__ __forceinline__ void cnt_arrive_release(unsigned* p) {
    asm volatile("red.release.gpu.global.add.u32 [%0], %1;"
                 :: "l"(p), "r"(1u) : "memory");
}
__device__ __forceinline__ unsigned ld_acquire(const unsigned* p) {
    unsigned v;
    asm volatile("ld.acquire.gpu.global.u32 %0, [%1];"
                 : "=r"(v) : "l"(p) : "memory");
    return v;
}

// ---------------- fast gate math (MUFU-based) ----------------
__device__ __forceinline__ float sigm_f(float x) {
    return __fdividef(1.f, 1.f + __expf(-x));
}
__device__ __forceinline__ float tanh_f(float x) {
    float e = __expf(2.f * x);
    return 1.f - __fdividef(2.f, e + 1.f);
}

// ---------------- tf32 helpers ----------------
__device__ __forceinline__ unsigned tf32cvt(float f) {
    unsigned r; asm("cvt.rna.tf32.f32 %0, %1;" : "=r"(r) : "f"(f)); return r;
}
__device__ __forceinline__ void mma_tf32(float* d, const unsigned* a, const unsigned* b) {
    asm("mma.sync.aligned.m16n8k8.row.col.f32.tf32.tf32.f32 "
        "{%0,%1,%2,%3}, {%4,%5,%6,%7}, {%8,%9}, {%0,%1,%2,%3};"
        : "+f"(d[0]), "+f"(d[1]), "+f"(d[2]), "+f"(d[3])
        : "r"(a[0]), "r"(a[1]), "r"(a[2]), "r"(a[3]), "r"(b[0]), "r"(b[1]));
}

// =====================================================================
// Kernel 1 (tf32): Wx = x @ W_w^T + W_b.
// v2: K-chunk 16, double-buffered smem [2][128][20] (40 KB), ONE sync
// per chunk (store c -> sync -> prefetch c+1 || mma c), 2 blocks/SM.
// Fragment k-interleave within each 8-group: (f[t], f[t+4]) -> (2t, 2t+1).
// =====================================================================
__global__ void __launch_bounds__(256, 2) gemm_wx_tf32_kernel(
    const float* __restrict__ x, const float* __restrict__ Ww,
    const float* __restrict__ Wb)
{
    __shared__ __align__(16) unsigned As[2][128][20];
    __shared__ __align__(16) unsigned Bs[2][128][20];

    const int tid  = threadIdx.x;
    const int w    = tid >> 5;
    const int lane = tid & 31;
    const int g    = lane >> 2;
    const int tig  = lane & 3;
    const int wm   = w >> 1;
    const int wn   = w & 1;
    const int m0   = blockIdx.y * 128;
    const int n0   = blockIdx.x * 128;

    const int lr = tid >> 1;       // copy row 0..127
    const int lh = tid & 1;        // 8-group within 16-wide chunk

    float acc[2][8][4];
    #pragma unroll
    for (int mt = 0; mt < 2; mt++)
        #pragma unroll
        for (int nt = 0; nt < 8; nt++)
            #pragma unroll
            for (int c = 0; c < 4; c++) acc[mt][nt][c] = 0.f;

    // preload chunk 0 (8 floats per matrix per thread)
    float4 ra[2], rb[2];
    {
        const float* pa = &x [(size_t)(m0 + lr) * 512 + lh * 8];
        const float* pb = &Ww[(size_t)(n0 + lr) * 512 + lh * 8];
        ra[0] = *(const float4*)(pa);     ra[1] = *(const float4*)(pa + 4);
        rb[0] = *(const float4*)(pb);     rb[1] = *(const float4*)(pb + 4);
    }

    for (int chunk = 0; chunk < 32; chunk++) {
        const int buf = chunk & 1;
        // store chunk (cvt + interleave): positions base..base+7, base = lh*8
        {
            const float* f  = (const float*)ra;
            const float* fw = (const float*)rb;
            const int base = lh * 8;
            uint4 v0 = make_uint4(tf32cvt(f[0]), tf32cvt(f[4]), tf32cvt(f[1]), tf32cvt(f[5]));
            uint4 v1 = make_uint4(tf32cvt(f[2]), tf32cvt(f[6]), tf32cvt(f[3]), tf32cvt(f[7]));
            *(uint4*)&As[buf][lr][base]     = v0;
            *(uint4*)&As[buf][lr][base + 4] = v1;
            uint4 w0 = make_uint4(tf32cvt(fw[0]), tf32cvt(fw[4]), tf32cvt(fw[1]), tf32cvt(fw[5]));
            uint4 w1 = make_uint4(tf32cvt(fw[2]), tf32cvt(fw[6]), tf32cvt(fw[3]), tf32cvt(fw[7]));
            *(uint4*)&Bs[buf][lr][base]     = w0;
            *(uint4*)&Bs[buf][lr][base + 4] = w1;
        }
        __syncthreads();   // chunk's tiles visible; prior mma on other buffer done

        // prefetch next chunk (overlaps the MMA below)
        if (chunk < 31) {
            const int kc = (chunk + 1) * 16;
            const float* pa = &x [(size_t)(m0 + lr) * 512 + kc + lh * 8];
            const float* pb = &Ww[(size_t)(n0 + lr) * 512 + kc + lh * 8];
            ra[0] = *(const float4*)(pa);     ra[1] = *(const float4*)(pa + 4);
            rb[0] = *(const float4*)(pb);     rb[1] = *(const float4*)(pb + 4);
        }

        // 2 k-steps of m16n8k8 on this buffer
        #pragma unroll
        for (int s = 0; s < 2; s++) {
            const int koff = 8 * s + 2 * tig;
            unsigned afrag[2][4];
            #pragma unroll
            for (int mt = 0; mt < 2; mt++) {
                const int rowA = wm * 32 + mt * 16 + g;
                uint2 p1 = *(const uint2*)&As[buf][rowA][koff];
                uint2 p2 = *(const uint2*)&As[buf][rowA + 8][koff];
                afrag[mt][0] = p1.x; afrag[mt][1] = p2.x;
                afrag[mt][2] = p1.y; afrag[mt][3] = p2.y;
            }
            #pragma unroll
            for (int nt = 0; nt < 8; nt++) {
                const int rowB = wn * 64 + nt * 8 + g;
                uint2 bp = *(const uint2*)&Bs[buf][rowB][koff];
                unsigned bfrag[2] = { bp.x, bp.y };
                mma_tf32(acc[0][nt], afrag[0], bfrag);
                mma_tf32(acc[1][nt], afrag[1], bfrag);
            }
        }
    }

    // epilogue: add bias, write g_wx
    #pragma unroll
    for (int nt = 0; nt < 8; nt++) {
        const int colD = n0 + wn * 64 + nt * 8 + 2 * tig;
        const float2 wb2 = *(const float2*)&Wb[colD];
        #pragma unroll
        for (int mt = 0; mt < 2; mt++) {
            const int rowD = m0 + wm * 32 + mt * 16 + g;
            float2 lo = make_float2(acc[mt][nt][0] + wb2.x, acc[mt][nt][1] + wb2.y);
            float2 hi = make_float2(acc[mt][nt][2] + wb2.x, acc[mt][nt][3] + wb2.y);
            *(float2*)&g_wx[(size_t)rowD * FOURH + colD]       = lo;
            *(float2*)&g_wx[(size_t)(rowD + 8) * FOURH + colD] = hi;
        }
    }
}

// =====================================================================
// Kernel 2: persistent recurrent sLSTM — R12 VERBATIM (best measured:
// 4 sync domains, distributed finalize, tid0 poll, 1 RED/block/step).
// =====================================================================
__global__ void __launch_bounds__(512) lstm_rec_kernel(
    const float* __restrict__ Uw, const float* __restrict__ Ub,
    const float* __restrict__ alpha, float* __restrict__ out)
{
    __shared__ __align__(16) float h_s[2][Hh];    // 4 KB: this domain's 2 h rows

    const int tid  = threadIdx.x;
    const int w    = tid >> 5;
    const int lane = tid & 31;
    const int blk  = blockIdx.x;
    const int dom  = blk >> 5;
    const int j0   = (blk & 31) * 16;
    const int B0   = 2 * dom;
    const int jg   = j0 + w;        // this warp's hidden unit

    // lane slot: m = (lane>>2)&7 -> gate, batch-half
    const int m    = (lane >> 2) & 7;
    const int g_l  = m & 3;
    const int bi_l = m >> 2;
    const int Bf   = B0 + bi_l;

    // U_w register-resident: rows (g, jg) g=0..3; lane cols 4*lane + 128*q
    ulonglong2 u[4][4];
    #pragma unroll
    for (int g = 0; g < 4; g++)
        #pragma unroll
        for (int q = 0; q < 4; q++)
            u[g][q] = *(const ulonglong2*)&Uw[(size_t)(g * Hh + jg) * Hh + 128 * q + 4 * lane];

    const float ub_r    = Ub[g_l * Hh + jg];
    const float alpha_r = alpha[jg];
    float c_st = 0.f;               // live in lanes 0 (batch B0) and 16 (B0+1)

    unsigned* const my_cnt = &g_cnt4[dom * 32];

    // publish h0 = 0: warp 0 zeroes this block's 32 floats (16 units x 2 batches)
    if (w == 0) {
        g_h[0][(B0 + (lane & 1)) * Hh + j0 + (lane >> 1)] = 0.f;
        __syncwarp();
        if (lane == 0) cnt_arrive_release(my_cnt);
    }
    __syncthreads();

    for (int t = 0; t < Tt; ++t) {
        // prefetch Wx_t for this lane's slot (independent of h; L1-cached)
        const float wx = __ldg(&g_wx[((size_t)Bf * Tt + t) * FOURH + g_l * Hh + jg]);

        // ---- domain barrier: all 32 blocks of this domain published h_t
        if (tid == 0) {
            const unsigned tgt = (unsigned)DOM_BLKS * (unsigned)(t + 1);
            int spins = 0;
            while (ld_acquire(my_cnt) < tgt) {
                if (++spins > 64) __nanosleep(64);
            }
        }
        __syncthreads();

        // ---- stage this domain's 2 h rows (4 KB; L2-only loads)
        if (tid < 256) {
            const float4* src = (const float4*)&g_h[t & 1][B0 * Hh];
            ((float4*)&h_s[0][0])[tid] = __ldcg(&src[tid]);
        }
        __syncthreads();

        // ---- dots: 4 gates x 2 batches over full 512 cols (from smem)
        u64 acc[4][2];
        #pragma unroll
        for (int g = 0; g < 4; g++) { acc[g][0] = 0ull; acc[g][1] = 0ull; }
        #pragma unroll
        for (int b2 = 0; b2 < 2; b2++) {
            #pragma unroll
            for (int q = 0; q < 4; q++) {
                ulonglong2 h2 = *(const ulonglong2*)&h_s[b2][128 * q + 4 * lane];
                #pragma unroll
                for (int g = 0; g < 4; g++) {
                    fma2(acc[g][b2], u[g][q].x, h2.x);
                    fma2(acc[g][b2], u[g][q].y, h2.y);
                }
            }
        }

        // collapse pair halves -> v[mm], mm = gate + 4*batchhalf
        float v[8];
        #pragma unroll
        for (int g = 0; g < 4; g++)
            #pragma unroll
            for (int b2 = 0; b2 < 2; b2++) {
                float lo, hi; unpack2(acc[g][b2], lo, hi);
                v[g + 4 * b2] = lo + hi;
            }

        // 9-shfl butterfly: lane L ends with total for mm = (L>>2)&7
        {
            const bool up16 = (lane & 16) != 0;
            #pragma unroll
            for (int i = 0; i < 4; i++) {
                float a = v[i], bv = v[i + 4];
                float mine = up16 ? bv : a, oth = up16 ? a : bv;
                v[i] = mine + __shfl_xor_sync(0xffffffffu, oth, 16);
            }
            const bool up8 = (lane & 8) != 0;
            #pragma unroll
            for (int i = 0; i < 2; i++) {
                float a = v[i], bv = v[i + 2];
                float mine = up8 ? bv : a, oth = up8 ? a : bv;
                v[i] = mine + __shfl_xor_sync(0xffffffffu, oth, 8);
            }
            const bool up4 = (lane & 4) != 0;
            {
                float a = v[0], bv = v[1];
                float mine = up4 ? bv : a, oth = up4 ? a : bv;
                v[0] = mine + __shfl_xor_sync(0xffffffffu, oth, 4);
            }
            v[0] += __shfl_xor_sync(0xffffffffu, v[0], 2);
            v[0] += __shfl_xor_sync(0xffffffffu, v[0], 1);
        }

        // parallel activations: each lane activates its own slot
        const float z = v[0] + wx + ub_r;
        const float a = (g_l == 3) ? tanh_f(z) : sigm_f(z);

        // gather i/f/o/g at lanes 0 (bi=0) and 16 (bi=1); update c; store h
        const float a_f = __shfl_down_sync(0xffffffffu, a, 4);
        const float a_o = __shfl_down_sync(0xffffffffu, a, 8);
        const float a_g = __shfl_down_sync(0xffffffffu, a, 12);
        float hv = 0.f;
        if ((lane & 15) == 0) {
            c_st = alpha_r * (a_f * c_st + a * a_g);
            hv = a_o * tanh_f(c_st);
            g_h[(t + 1) & 1][Bf * Hh + jg] = hv;
        }

        // ---- all warps' h stores done -> single release-RED per block
        __syncthreads();
        if (tid == 0) cnt_arrive_release(my_cnt);

        // off-critical-path stores (kernel-end fence covers visibility)
        if ((lane & 15) == 0) {
            out[((size_t)Bf * Tt + t) * Hh + jg] = hv;
            if (t == Tt - 1) {
                out[(size_t)Bb * Tt * Hh + Bf * Hh + jg] = hv;                      // final h
                out[(size_t)Bb * Tt * Hh + (size_t)Bb * Hh + Bf * Hh + jg] = c_st;  // final c
            }
        }
    }

    // domain's slice-0 block resets its counter once all arrivals landed
    if ((blk & 31) == 0 && tid == 0) {
        const unsigned fin = (unsigned)DOM_BLKS * (unsigned)(Tt + 1);
        int spins = 0;
        while (ld_acquire(my_cnt) < fin) {
            if (++spins > 64) __nanosleep(128);
        }
        *my_cnt = 0u;
    }
}

// =====================================================================
extern "C" void kernel_launch(void* const* d_in, const int* in_sizes, int n_in,
                              void* d_out, int out_size)
{
    const float* x     = (const float*)d_in[0];
    const float* Ww    = (const float*)d_in[1];
    const float* Wb    = (const float*)d_in[2];
    const float* Uw    = (const float*)d_in[3];
    const float* Ub    = (const float*)d_in[4];
    const float* alpha = (const float*)d_in[5];
    float* out = (float*)d_out;

    dim3 ggrid(FOURH / 128, (Bb * Tt) / 128);   // 16 x 128
    gemm_wx_tf32_kernel<<<ggrid, 256>>>(x, Ww, Wb);
    lstm_rec_kernel<<<GRID_R, 512>>>(Uw, Ub, alpha, out);
}